// round 1
// baseline (speedup 1.0000x reference)
#include <cuda_runtime.h>
#include <cstdint>
#include <cstddef>

// Shapes (fixed by the problem)
//  x   [32, 64, 512, 64]  fp32
//  adj [512, 512]
//  ds  [32, 512, 512]
//  W   [64, 192]   (f = c*3 + k)
//  b   [64]
//  out [32, 64, 512, 64]

#define NB   32
#define NN   512
#define NL   64
#define NC   64      // c_in == c_out
#define NF   192     // K * c_in

// Scratch (device globals: allocation-free rule)
__device__ float g_T2[NN * NN];                          // 1 MB
__device__ float g_z[(size_t)NB * NF * NN * NL];         // [(b*192 + o*3 + k)][n][l], ~805 MB

// ---------------------------------------------------------------------------
// K1: T2 = 2 * adj @ adj - I   (0.27 GFLOP, trivial)
// ---------------------------------------------------------------------------
__global__ void k1_T2(const float* __restrict__ adj) {
    __shared__ float As[16][16];
    __shared__ float Bs[16][17];
    const int tx = threadIdx.x, ty = threadIdx.y;
    const int q = blockIdx.y * 16 + ty;
    const int n = blockIdx.x * 16 + tx;
    float acc = 0.f;
    for (int t0 = 0; t0 < NN; t0 += 16) {
        As[ty][tx] = adj[(size_t)q * NN + t0 + tx];
        Bs[ty][tx] = adj[(size_t)(t0 + ty) * NN + n];
        __syncthreads();
#pragma unroll
        for (int j = 0; j < 16; j++) acc = fmaf(As[ty][j], Bs[j][tx], acc);
        __syncthreads();
    }
    g_T2[(size_t)q * NN + n] = 2.f * acc - (q == n ? 1.f : 0.f);
}

// ---------------------------------------------------------------------------
// K2: z[b][f][m] = sum_c Wr[f][c] * x[b][c][m],  f = o*3+k, m = n*64+l (32768)
//     Wr[f][c] = W[(f/3)*192 + c*3 + (f%3)]
// block: 64f x 64m tile, 256 threads, 4x4 register tile, K=64 in one shot
// ---------------------------------------------------------------------------
__global__ __launch_bounds__(256) void k2_mix(const float* __restrict__ x,
                                              const float* __restrict__ W) {
    __shared__ float Ws[64][64];   // [c][f_local]
    __shared__ float Xs[64][64];   // [c][m_local]
    const int b  = blockIdx.z;
    const int f0 = blockIdx.y * 64;
    const int m0 = blockIdx.x * 64;
    const int t  = threadIdx.x;

    // Load W tile (tiny, cached)
#pragma unroll
    for (int i = 0; i < 16; i++) {
        int e = t + i * 256;            // 0..4095
        int c = e >> 6, fl = e & 63;
        int f = f0 + fl;
        Ws[c][fl] = W[(f / 3) * NF + c * 3 + (f % 3)];
    }
    // Load X tile (vectorized, coalesced)
#pragma unroll
    for (int i = 0; i < 4; i++) {
        int e = t + i * 256;            // 0..1023 float4s
        int c = e >> 4, mv = e & 15;
        const float* src = x + ((size_t)(b * NC + c)) * 32768 + m0;
        *(float4*)&Xs[c][mv * 4] = ((const float4*)src)[mv];
    }
    __syncthreads();

    const int tm = t & 15, tf = t >> 4;
    float acc[4][4];
#pragma unroll
    for (int i = 0; i < 4; i++)
#pragma unroll
        for (int j = 0; j < 4; j++) acc[i][j] = 0.f;

#pragma unroll
    for (int c = 0; c < 64; c++) {
        float4 a  = *(const float4*)&Ws[c][tf * 4];
        float4 bv = *(const float4*)&Xs[c][tm * 4];
        float av[4] = {a.x, a.y, a.z, a.w};
        float bb[4] = {bv.x, bv.y, bv.z, bv.w};
#pragma unroll
        for (int i = 0; i < 4; i++)
#pragma unroll
            for (int j = 0; j < 4; j++)
                acc[i][j] = fmaf(av[i], bb[j], acc[i][j]);
    }

#pragma unroll
    for (int i = 0; i < 4; i++) {
        int f = f0 + tf * 4 + i;
        float4 v = make_float4(acc[i][0], acc[i][1], acc[i][2], acc[i][3]);
        *(float4*)&g_z[((size_t)b * NF + f) * 32768 + m0 + tm * 4] = v;
    }
}

// ---------------------------------------------------------------------------
// K3: per (b, 4-o tile, 64-q tile):
//   out[q, (o,l)] = sum over kk=0..127 (8 n's each):
//      first 64 steps:  A[q,n]=ds[b,q,n]*adj[q,n], B=z(k=1)
//      last  64 steps:  A[q,n]=ds[b,q,n]*T2[q,n],  B=z(k=2)
//   epilogue: + bias[o] + ds[b,q,q]*z(k=0)[b,o,q,l]
// 256 threads, 8x8 register tile per thread, double-buffered smem
// ---------------------------------------------------------------------------
__global__ __launch_bounds__(256) void k3_main(const float* __restrict__ ds,
                                               const float* __restrict__ adj,
                                               const float* __restrict__ bias,
                                               float* __restrict__ out) {
    __shared__ float As[2][8][64];    // [buf][n_local][q_local]
    __shared__ float Bs[2][8][256];   // [buf][n_local][col]   col=(o_local*64+l)

    const int qt = blockIdx.x, ot = blockIdx.y, b = blockIdx.z;
    const int q0 = qt * 64, o0 = ot * 4;
    const int t = threadIdx.x;
    const int tcol = t & 31, tq = t >> 5;

    const float* dsb = ds + (size_t)b * NN * NN;

    // B-load geometry (constant per thread): rows j0 and j0+4, column group (ol,l)
    const int j0 = t >> 6;                       // 0..3
    const int ol = (t >> 4) & 3;                 // o_local 0..3
    const int l4 = (t & 15) * 4;                 // l base
    const size_t zb = ((size_t)(b * NC + o0 + ol) * 3) * 32768 + l4;

    float acc[8][8];
#pragma unroll
    for (int i = 0; i < 8; i++)
#pragma unroll
        for (int j = 0; j < 8; j++) acc[i][j] = 0.f;

    float4 pd0, pd1, pm0, pm1, pb0, pb1;

#define K3_LOAD(KK)                                                         \
    {                                                                       \
        int half = ((KK) < 64) ? 1 : 0;                                     \
        int n0 = ((KK) & 63) << 3;                                          \
        if (t < 64) {                                                       \
            const float* dp = dsb + (size_t)(q0 + t) * NN + n0;             \
            pd0 = *(const float4*)dp;                                       \
            pd1 = *(const float4*)(dp + 4);                                 \
            const float* mbase = half ? adj : g_T2;                         \
            const float* mp = mbase + (size_t)(q0 + t) * NN + n0;           \
            pm0 = *(const float4*)mp;                                       \
            pm1 = *(const float4*)(mp + 4);                                 \
        }                                                                   \
        size_t koff = (size_t)(half ? 1 : 2) * 32768;                       \
        pb0 = *(const float4*)&g_z[zb + koff + (size_t)(n0 + j0) * 64];     \
        pb1 = *(const float4*)&g_z[zb + koff + (size_t)(n0 + j0 + 4) * 64]; \
    }

#define K3_STORE(BUF)                                       \
    {                                                       \
        if (t < 64) {                                       \
            As[BUF][0][t] = pd0.x * pm0.x;                  \
            As[BUF][1][t] = pd0.y * pm0.y;                  \
            As[BUF][2][t] = pd0.z * pm0.z;                  \
            As[BUF][3][t] = pd0.w * pm0.w;                  \
            As[BUF][4][t] = pd1.x * pm1.x;                  \
            As[BUF][5][t] = pd1.y * pm1.y;                  \
            As[BUF][6][t] = pd1.z * pm1.z;                  \
            As[BUF][7][t] = pd1.w * pm1.w;                  \
        }                                                   \
        *(float4*)&Bs[BUF][j0][(t & 63) * 4] = pb0;         \
        *(float4*)&Bs[BUF][j0 + 4][(t & 63) * 4] = pb1;     \
    }

    K3_LOAD(0);
    K3_STORE(0);
    __syncthreads();

    for (int kk = 0; kk < 128; kk++) {
        int cur = kk & 1;
        if (kk < 127) K3_LOAD(kk + 1);
#pragma unroll
        for (int j = 0; j < 8; j++) {
            float4 a0 = *(const float4*)&As[cur][j][tq * 4];
            float4 a1 = *(const float4*)&As[cur][j][32 + tq * 4];
            float4 b0 = *(const float4*)&Bs[cur][j][tcol * 4];
            float4 b1 = *(const float4*)&Bs[cur][j][128 + tcol * 4];
            float av[8] = {a0.x, a0.y, a0.z, a0.w, a1.x, a1.y, a1.z, a1.w};
            float bv[8] = {b0.x, b0.y, b0.z, b0.w, b1.x, b1.y, b1.z, b1.w};
#pragma unroll
            for (int qi = 0; qi < 8; qi++)
#pragma unroll
                for (int ci = 0; ci < 8; ci++)
                    acc[qi][ci] = fmaf(av[qi], bv[ci], acc[qi][ci]);
        }
        if (kk < 127) K3_STORE(cur ^ 1);
        __syncthreads();
    }

    // Epilogue: + bias[o] + ds[b,q,q] * z0[b,o,q,l]
#pragma unroll
    for (int qi = 0; qi < 8; qi++) {
        int q = q0 + ((qi < 4) ? (tq * 4 + qi) : (32 + tq * 4 + qi - 4));
        float dqq = dsb[(size_t)q * NN + q];
#pragma unroll
        for (int g = 0; g < 2; g++) {
            int col = g * 128 + tcol * 4;
            int o = o0 + (col >> 6);
            int l = col & 63;
            float4 z0 = *(const float4*)&g_z[((size_t)(b * NC + o) * 3) * 32768 +
                                             (size_t)q * 64 + l];
            float bo = bias[o];
            float4 r;
            r.x = fmaf(dqq, z0.x, acc[qi][g * 4 + 0] + bo);
            r.y = fmaf(dqq, z0.y, acc[qi][g * 4 + 1] + bo);
            r.z = fmaf(dqq, z0.z, acc[qi][g * 4 + 2] + bo);
            r.w = fmaf(dqq, z0.w, acc[qi][g * 4 + 3] + bo);
            *(float4*)&out[(((size_t)b * NC + o) * NN + q) * NL + l] = r;
        }
    }
#undef K3_LOAD
#undef K3_STORE
}

// ---------------------------------------------------------------------------
extern "C" void kernel_launch(void* const* d_in, const int* in_sizes, int n_in,
                              void* d_out, int out_size) {
    const float* x    = (const float*)d_in[0];
    const float* adj  = (const float*)d_in[1];
    const float* ds   = (const float*)d_in[2];
    const float* W    = (const float*)d_in[3];
    const float* bias = (const float*)d_in[4];
    float* out = (float*)d_out;

    k1_T2<<<dim3(32, 32), dim3(16, 16)>>>(adj);
    k2_mix<<<dim3(512, 3, 32), 256>>>(x, W);
    // blockIdx.x = q-tile so consecutive blocks share the same z-slice (L2 reuse)
    k3_main<<<dim3(8, 16, 32), 256>>>(ds, adj, bias, out);
}